// round 4
// baseline (speedup 1.0000x reference)
#include <cuda_runtime.h>

#define NFFT 1024
#define TPB  128
// Skew on float2 word index: conflict-free for stride-8 writes, <=2-way elsewhere
#define SKQ(a) ((a) + ((a) >> 3))

// In-place inverse DFT-8 (twiddle sign +i).
__device__ __forceinline__ void radix8_inv(float* r, float* i)
{
    const float RQ = 0.7071067811865476f;
    float e0r = r[0] + r[4], e0i = i[0] + i[4];
    float e1r = r[0] - r[4], e1i = i[0] - i[4];
    float e2r = r[2] + r[6], e2i = i[2] + i[6];
    float e3r = r[2] - r[6], e3i = i[2] - i[6];
    float E0r = e0r + e2r, E0i = e0i + e2i;
    float E2r = e0r - e2r, E2i = e0i - e2i;
    float E1r = e1r - e3i, E1i = e1i + e3r;
    float E3r = e1r + e3i, E3i = e1i - e3r;
    float o0r = r[1] + r[5], o0i = i[1] + i[5];
    float o1r = r[1] - r[5], o1i = i[1] - i[5];
    float o2r = r[3] + r[7], o2i = i[3] + i[7];
    float o3r = r[3] - r[7], o3i = i[3] - i[7];
    float O0r = o0r + o2r, O0i = o0i + o2i;
    float O2r = o0r - o2r, O2i = o0i - o2i;
    float O1r = o1r - o3i, O1i = o1i + o3r;
    float O3r = o1r + o3i, O3i = o1i - o3r;
    float T1r = RQ * (O1r - O1i), T1i = RQ * (O1r + O1i);
    float T2r = -O2i,             T2i = O2r;
    float T3r = -RQ * (O3r + O3i), T3i = RQ * (O3r - O3i);
    r[0] = E0r + O0r; i[0] = E0i + O0i;
    r[4] = E0r - O0r; i[4] = E0i - O0i;
    r[1] = E1r + T1r; i[1] = E1i + T1i;
    r[5] = E1r - T1r; i[5] = E1i - T1i;
    r[2] = E2r + T2r; i[2] = E2i + T2i;
    r[6] = E2r - T2r; i[6] = E2i - T2i;
    r[3] = E3r + T3r; i[3] = E3i + T3i;
    r[7] = E3r - T3r; i[7] = E3i - T3i;
}

__device__ __forceinline__ void twiddle_chain(float* xr, float* xi,
                                              float wr, float wi)
{
    float cwr = wr, cwi = wi;
    #pragma unroll
    for (int c = 1; c < 8; c++) {
        float tr = xr[c] * cwr - xi[c] * cwi;
        xi[c]    = xr[c] * cwi + xi[c] * cwr;
        xr[c]    = tr;
        if (c < 7) {
            float nr = cwr * wr - cwi * wi;
            cwi      = cwr * wi + cwi * wr;
            cwr      = nr;
        }
    }
}

__global__ __launch_bounds__(TPB)
void ifft1024_v4(const float* __restrict__ xre,
                 const float* __restrict__ xim,
                 float* __restrict__ ore,
                 float* __restrict__ oim)
{
    __shared__ float2 sA[NFFT + NFFT / 8];
    __shared__ float2 sB[NFFT + NFFT / 8];

    const int t = threadIdx.x;
    const size_t base = (size_t)blockIdx.x * NFFT;
    const float scale = 1.0f / (float)NFFT;
    const float TWO_PI = 6.283185307179586f;

    float zr[8], zi[8];

    // ---------- stage 0: radix-8, M=1 (coalesced global read) ----------
    #pragma unroll
    for (int c = 0; c < 8; c++) {
        zr[c] = __ldcs(xre + base + t + 128 * c) * scale;
        zi[c] = __ldcs(xim + base + t + 128 * c) * scale;
    }
    radix8_inv(zr, zi);
    #pragma unroll
    for (int c = 0; c < 8; c++)
        sA[SKQ(8 * t + c)] = make_float2(zr[c], zi[c]);
    __syncthreads();

    // ---------- stage 1: radix-8, M=8 ----------
    #pragma unroll
    for (int c = 0; c < 8; c++) {
        float2 v = sA[SKQ(t + 128 * c)];
        zr[c] = v.x; zi[c] = v.y;
    }
    {
        float wr, wi;
        __sincosf(TWO_PI * (float)(t & 7) * (1.0f / 64.0f), &wi, &wr);
        twiddle_chain(zr, zi, wr, wi);
    }
    radix8_inv(zr, zi);
    {
        int wb = (t & 7) + ((t >> 3) << 6);
        #pragma unroll
        for (int c = 0; c < 8; c++)
            sB[SKQ(wb + 8 * c)] = make_float2(zr[c], zi[c]);
    }
    __syncthreads();

    // ---------- stage 2: radix-8, M=64, with permuted butterfly index ----------
    // j6 = t4 so the stage-3 partner (j ^ 64) lives at lane t ^ 16 (same warp).
    const int j = (t & 15) | ((t & 0x60) >> 1) | ((t & 16) << 2);
    #pragma unroll
    for (int c = 0; c < 8; c++) {
        float2 v = sB[SKQ(j + 128 * c)];
        zr[c] = v.x; zi[c] = v.y;
    }
    {
        float wr, wi;
        __sincosf(TWO_PI * (float)(j & 63) * (1.0f / 512.0f), &wi, &wr);
        twiddle_chain(zr, zi, wr, wi);
    }
    radix8_inv(zr, zi);
    // thread j's outputs sit at positions (j&63) + 64c + 512*(j>>6)

    // ---------- stage 3: radix-2, M=512, via shfl_xor(16), store global ----------
    const int b  = j & 63;
    const int ht = j >> 6;

    float rr[4], ri[4];
    #pragma unroll
    for (int q = 0; q < 4; q++) {
        // ht=0 gives its c=4..7 (partner computes those pairs); ht=1 gives c=0..3
        float sr_ = ht ? zr[q] : zr[4 + q];
        float si_ = ht ? zi[q] : zi[4 + q];
        rr[q] = __shfl_xor_sync(0xffffffffu, sr_, 16);
        ri[q] = __shfl_xor_sync(0xffffffffu, si_, 16);
    }

    // w_k = exp(+2*pi*i*k/1024), k = b + 64c, starting at c = 4*ht
    float wr, wi;
    __sincosf(TWO_PI * (float)(b + 256 * ht) * (1.0f / 1024.0f), &wi, &wr);
    const float c64 = 0.9238795325112867f;   // cos(pi/8)
    const float s64 = 0.3826834323650898f;   // sin(pi/8)

    #pragma unroll
    for (int q = 0; q < 4; q++) {
        const int c = 4 * ht + q;
        // low  = element at k      (held by ht=0 side)
        // high = element at k+512  (held by ht=1 side)
        float lr = ht ? rr[q] : zr[q];
        float li = ht ? ri[q] : zi[q];
        float hr = ht ? zr[c] : rr[q];
        float hi = ht ? zi[c] : ri[q];

        float tr = hr * wr - hi * wi;
        float ti = hr * wi + hi * wr;

        const size_t k = base + (size_t)(b + 64 * c);
        __stcs(ore + k,       lr + tr);
        __stcs(oim + k,       li + ti);
        __stcs(ore + k + 512, lr - tr);
        __stcs(oim + k + 512, li - ti);

        if (q < 3) {
            float nr = wr * c64 - wi * s64;
            wi       = wr * s64 + wi * c64;
            wr       = nr;
        }
    }
}

extern "C" void kernel_launch(void* const* d_in, const int* in_sizes, int n_in,
                              void* d_out, int out_size)
{
    const float* re = (const float*)d_in[0];
    const float* im = (const float*)d_in[1];
    float* out = (float*)d_out;

    const int n_elems = in_sizes[0];      // 8*4096*1024
    const int rows    = n_elems / NFFT;   // 32768

    float* ore = out;
    float* oim = out + (size_t)n_elems;

    ifft1024_v4<<<rows, TPB>>>(re, im, ore, oim);
}

// round 5
// speedup vs baseline: 1.3591x; 1.3591x over previous
#include <cuda_runtime.h>

#define NFFT 1024
#define TPB  128
// float2-word skew: conflict-free for ALL four access patterns used below
#define SK(a) ((a) + ((a) >> 4))

#define CMUL(r, i, cr, ci) { float _t = (r)*(cr) - (i)*(ci); (i) = (r)*(ci) + (i)*(cr); (r) = _t; }

// Inverse 4-pt DFT (twiddle sign +i), outputs in natural order.
__device__ __forceinline__ void idft4(
    float ar, float ai, float br, float bi,
    float cr, float ci, float dr, float di,
    float& o0r, float& o0i, float& o1r, float& o1i,
    float& o2r, float& o2i, float& o3r, float& o3i)
{
    float t0r = ar + cr, t0i = ai + ci;
    float t1r = ar - cr, t1i = ai - ci;
    float t2r = br + dr, t2i = bi + di;
    float t3r = br - dr, t3i = bi - di;
    o0r = t0r + t2r;  o0i = t0i + t2i;
    o2r = t0r - t2r;  o2i = t0i - t2i;
    o1r = t1r - t3i;  o1i = t1i + t3r;   // + i*t3
    o3r = t1r + t3i;  o3i = t1i - t3r;   // - i*t3
}

// Inverse 16-pt DFT (sign +i), natural-order in/out, via 4x4 decomposition.
__device__ __forceinline__ void idft16(const float* xr, const float* xi,
                                       float* Xr, float* Xi)
{
    const float C1 = 0.9238795325112867f;   // cos(pi/8)
    const float S1 = 0.3826834323650898f;   // sin(pi/8)
    const float C2 = 0.7071067811865476f;

    float yr[16], yi[16];
    #pragma unroll
    for (int n0 = 0; n0 < 4; n0++) {
        idft4(xr[n0], xi[n0], xr[n0+4], xi[n0+4],
              xr[n0+8], xi[n0+8], xr[n0+12], xi[n0+12],
              yr[n0], yi[n0], yr[n0+4], yi[n0+4],
              yr[n0+8], yi[n0+8], yr[n0+12], yi[n0+12]);
    }
    // z[n0][m] = y[n0][m] * W16^{n0*m} (stored at n0+4m), W16 = e^{+i*pi/8}
    CMUL(yr[5],  yi[5],   C1,  S1);   // (1,1) W^1
    CMUL(yr[9],  yi[9],   C2,  C2);   // (1,2) W^2
    CMUL(yr[13], yi[13],  S1,  C1);   // (1,3) W^3
    CMUL(yr[6],  yi[6],   C2,  C2);   // (2,1) W^2
    { float t = yr[10]; yr[10] = -yi[10]; yi[10] = t; }   // (2,2) W^4 = i
    CMUL(yr[14], yi[14], -C2,  C2);   // (2,3) W^6
    CMUL(yr[7],  yi[7],   S1,  C1);   // (3,1) W^3
    CMUL(yr[11], yi[11], -C2,  C2);   // (3,2) W^6
    CMUL(yr[15], yi[15], -C1, -S1);   // (3,3) W^9 = -W^1
    // X[m+4p] = IDFT4 over n0 of z[n0][m]
    #pragma unroll
    for (int m = 0; m < 4; m++) {
        idft4(yr[4*m+0], yi[4*m+0], yr[4*m+1], yi[4*m+1],
              yr[4*m+2], yi[4*m+2], yr[4*m+3], yi[4*m+3],
              Xr[m],    Xi[m],    Xr[m+4],  Xi[m+4],
              Xr[m+8],  Xi[m+8],  Xr[m+12], Xi[m+12]);
    }
}

__global__ __launch_bounds__(TPB)
void ifft1024_v5(const float* __restrict__ xre,
                 const float* __restrict__ xim,
                 float* __restrict__ ore,
                 float* __restrict__ oim)
{
    __shared__ float2 sm[2][1088];   // 1024 + skew padding, per row

    const int tid = threadIdx.x;
    const int lr  = tid >> 6;        // local row 0/1
    const int t   = tid & 63;        // thread within row
    float2* s = sm[lr];
    const size_t base = ((size_t)blockIdx.x * 2 + lr) * NFFT;
    const float scale = 1.0f / (float)NFFT;
    const float TWO_PI = 6.283185307179586f;

    float xr[16], xi[16], Xr[16], Xi[16];

    // ============ stage 0: radix-16, L=1 (global read, coalesced) ============
    #pragma unroll
    for (int c = 0; c < 16; c++) {
        xr[c] = xre[base + t + 64 * c] * scale;
        xi[c] = xim[base + t + 64 * c] * scale;
    }
    idft16(xr, xi, Xr, Xi);
    #pragma unroll
    for (int c = 0; c < 16; c++)
        s[SK(16 * t + c)] = make_float2(Xr[c], Xi[c]);
    __syncthreads();

    // ============ stage 1: radix-16, L=16 (in-place: read-all, sync, write) ============
    #pragma unroll
    for (int c = 0; c < 16; c++) {
        float2 v = s[SK(t + 64 * c)];
        xr[c] = v.x;  xi[c] = v.y;
    }
    __syncthreads();
    {   // twiddle: x[c] *= W256^{b*c}, b = t mod 16, W256 = e^{+2*pi*i/256}
        const int b = t & 15;
        float wr, wi;
        __sincosf(TWO_PI * (float)b * (1.0f / 256.0f), &wi, &wr);
        float cwr = wr, cwi = wi;
        #pragma unroll
        for (int c = 1; c < 16; c++) {
            CMUL(xr[c], xi[c], cwr, cwi);
            if (c < 15) { float nr = cwr*wr - cwi*wi; cwi = cwr*wi + cwi*wr; cwr = nr; }
        }
    }
    idft16(xr, xi, Xr, Xi);
    {
        const int wb = (t & 15) + ((t >> 4) << 8);   // b + 256*(t/16)
        #pragma unroll
        for (int c = 0; c < 16; c++)
            s[SK(wb + 16 * c)] = make_float2(Xr[c], Xi[c]);
    }
    __syncthreads();

    // ============ stage 2: radix-4, L=256, j = 4t+d, natural-order global store ============
    {
        float outR[4][4], outI[4][4];   // [k][d]
        // w_j = W1024^j chained across d from j = 4t
        float wr, wi;
        __sincosf(TWO_PI * (float)(4 * t) * (1.0f / 1024.0f), &wi, &wr);
        const float dc = 0.9999811752826011f;    // cos(2*pi/1024)
        const float ds = 0.006135884649154475f;  // sin(2*pi/1024)

        #pragma unroll
        for (int d = 0; d < 4; d++) {
            const int j = 4 * t + d;
            float ar[4], ai[4];
            #pragma unroll
            for (int k = 0; k < 4; k++) {
                float2 v = s[SK(j + 256 * k)];
                ar[k] = v.x;  ai[k] = v.y;
            }
            // twiddles w, w^2, w^3 on k = 1..3
            float w2r = wr*wr - wi*wi, w2i = 2.0f*wr*wi;
            float w3r = w2r*wr - w2i*wi, w3i = w2r*wi + w2i*wr;
            CMUL(ar[1], ai[1], wr,  wi);
            CMUL(ar[2], ai[2], w2r, w2i);
            CMUL(ar[3], ai[3], w3r, w3i);
            idft4(ar[0], ai[0], ar[1], ai[1], ar[2], ai[2], ar[3], ai[3],
                  outR[0][d], outI[0][d], outR[1][d], outI[1][d],
                  outR[2][d], outI[2][d], outR[3][d], outI[3][d]);
            if (d < 3) { float nr = wr*dc - wi*ds; wi = wr*ds + wi*dc; wr = nr; }
        }
        #pragma unroll
        for (int k = 0; k < 4; k++) {
            const size_t o = base + (size_t)(4 * t + 256 * k);
            *(float4*)&ore[o] = make_float4(outR[k][0], outR[k][1], outR[k][2], outR[k][3]);
            *(float4*)&oim[o] = make_float4(outI[k][0], outI[k][1], outI[k][2], outI[k][3]);
        }
    }
}

extern "C" void kernel_launch(void* const* d_in, const int* in_sizes, int n_in,
                              void* d_out, int out_size)
{
    const float* re = (const float*)d_in[0];
    const float* im = (const float*)d_in[1];
    float* out = (float*)d_out;

    const int n_elems = in_sizes[0];        // 8*4096*1024
    const int rows    = n_elems / NFFT;     // 32768

    float* ore = out;
    float* oim = out + (size_t)n_elems;

    ifft1024_v5<<<rows / 2, TPB>>>(re, im, ore, oim);
}